// round 10
// baseline (speedup 1.0000x reference)
#include <cuda_runtime.h>
#include <cuda_fp16.h>

// V=100000, K=32, F=64.
// out[v, 0:64]   = mean over K neighbours of x[idxs[v,k], :]
// out[v, 64:128] = max  over K neighbours
//
// Two kernels + PDL (R9 structure):
//   convert: x fp32 -> fp16 scratch (row = 128B = one cache line).
//   gather:  warp per vertex, one LDG per gathered row (whole warp covers
//            the row), HADD2/HMAX2 accumulate, coalesced float2 epilogue.
// R10 change: gather loads use ld.global.cg (L2-only, no L1 allocation).
// The gather has ~1% L1 hit rate, so every miss's L1 line fill + evict was
// pure overhead on the 128B/cyc L1 port (~3 cyc/line, matching the measured
// 72% L1 busy at 34us). .cg removes the fill traffic.

#define KNN  32
#define FDIM 64
#define VMAX 100000

__device__ __align__(16) __half2 g_xh[VMAX * (FDIM / 2)];   // 12.8 MB

__global__ __launch_bounds__(256)
void convert_kernel(const float4* __restrict__ x4, int n8)   // n8 = V*F/8
{
    int i = blockIdx.x * blockDim.x + threadIdx.x;
    if (i < n8) {
        float4 a = x4[2 * i];
        float4 b = x4[2 * i + 1];
        __half2 h0 = __floats2half2_rn(a.x, a.y);
        __half2 h1 = __floats2half2_rn(a.z, a.w);
        __half2 h2 = __floats2half2_rn(b.x, b.y);
        __half2 h3 = __floats2half2_rn(b.z, b.w);
        int4 packed;
        packed.x = *(const int*)&h0;
        packed.y = *(const int*)&h1;
        packed.z = *(const int*)&h2;
        packed.w = *(const int*)&h3;
        *reinterpret_cast<int4*>(&g_xh[4 * i]) = packed;
    }
    // Work done: allow dependent gather CTAs to start launching.
    asm volatile("griddepcontrol.launch_dependents;" ::: "memory");
}

__global__ __launch_bounds__(256, 8)   // pin 32-reg budget -> full occupancy
void knn_mean_max_kernel(const int* __restrict__ idxs,
                         float2*    __restrict__ out2,
                         int V)
{
    const int warp = (blockIdx.x * blockDim.x + threadIdx.x) >> 5;
    const int lane = threadIdx.x & 31;
    const bool active = (warp < V);

    // Prologue independent of convert's output: coalesced index load.
    int my_idx = 0;
    if (active) my_idx = idxs[warp * KNN + lane];

    // Block until convert's g_xh writes are visible.
    asm volatile("griddepcontrol.wait;" ::: "memory");

    if (!active) return;

    const __half2 zero = __float2half2_rn(0.0f);
    const __half2 ninf = __float2half2_rn(-65504.0f);
    __half2 sa = zero, sb = zero;      // two 16-deep fp16 sum chains
    __half2 m  = ninf;

    // Lane l reads half2 l of each gathered row (row = 32 half2 = 128B):
    // one LDG per row per warp -> exactly one cache line per instruction.
    const __half2* __restrict__ xl = g_xh + lane;

    #pragma unroll
    for (int k = 0; k < KNN; ++k) {
        const int idx = __shfl_sync(0xffffffffu, my_idx, k);
        const __half2* ptr = xl + (size_t)(unsigned)idx * (FDIM / 2);
        // L2-only load: no L1 line allocation / fill / evict.
        unsigned int u;
        asm("ld.global.cg.b32 %0, [%1];" : "=r"(u) : "l"(ptr));
        const __half2 h = *(const __half2*)&u;
        if (k & 1) sb = __hadd2(sb, h);
        else       sa = __hadd2(sa, h);
        m = __hmax2(m, h);
    }

    const float2 fa = __half22float2(sa);
    const float2 fb = __half22float2(sb);
    const float2 fm = __half22float2(m);
    const float inv = 1.0f / KNN;

    // out row = 128 floats = 64 float2: [mean 32 float2 | max 32 float2].
    out2[warp * FDIM + lane]      = make_float2((fa.x + fb.x) * inv,
                                                (fa.y + fb.y) * inv);
    out2[warp * FDIM + 32 + lane] = make_float2(fm.x, fm.y);
}

extern "C" void kernel_launch(void* const* d_in, const int* in_sizes, int n_in,
                              void* d_out, int out_size)
{
    const float4* x4   = (const float4*)d_in[0];  // x: [V, 64] float32
    const int*    idxs = (const int*)d_in[1];     // idxs: [V, 32] int32
    float2*       out2 = (float2*)d_out;          // out: [V, 128] float32

    const int V  = in_sizes[0] / FDIM;            // 100000
    const int n8 = in_sizes[0] / 8;               // V*F/8 (16B per thread)

    convert_kernel<<<(n8 + 255) / 256, 256>>>(x4, n8);

    const int warps_per_block = 256 / 32;         // 8
    const int blocks = (V + warps_per_block - 1) / warps_per_block;

    cudaLaunchConfig_t cfg = {};
    cfg.gridDim  = dim3((unsigned)blocks, 1, 1);
    cfg.blockDim = dim3(256, 1, 1);
    cfg.dynamicSmemBytes = 0;
    cfg.stream = 0;

    cudaLaunchAttribute attrs[1];
    attrs[0].id = cudaLaunchAttributeProgrammaticStreamSerialization;
    attrs[0].val.programmaticStreamSerializationAllowed = 1;
    cfg.attrs = attrs;
    cfg.numAttrs = 1;

    cudaLaunchKernelEx(&cfg, knn_mean_max_kernel, idxs, out2, V);
}

// round 11
// speedup vs baseline: 1.3292x; 1.3292x over previous
#include <cuda_runtime.h>
#include <cuda_fp16.h>

// V=100000, K=32, F=64.
// out[v, 0:64]   = mean over K neighbours of x[idxs[v,k], :]
// out[v, 64:128] = max  over K neighbours
//
// Two kernels + PDL (R9 structure).
// R11 gather coding: TWO vertices per warp, HALF-warp per gathered row.
//   Lane = 16*h + hl handles vertex v = 2*warp + h; lane loads 8B (LDG.64)
//   of each row -> 16 lanes cover the 128B line (one line per request, same
//   wavefront count as before) while idx loads / shuffles / stores amortize
//   over 2 vertices (~40% fewer instructions per vertex).
// Outputs stored with st.global.cs (streaming, evict-first) so the 51MB
// output stream doesn't evict the resident 12.8MB fp16 table from L2.

#define KNN  32
#define FDIM 64
#define VMAX 100000

__device__ __align__(16) __half2 g_xh[VMAX * (FDIM / 2)];   // 12.8 MB

__global__ __launch_bounds__(256)
void convert_kernel(const float4* __restrict__ x4, int n8)   // n8 = V*F/8
{
    int i = blockIdx.x * blockDim.x + threadIdx.x;
    if (i < n8) {
        float4 a = x4[2 * i];
        float4 b = x4[2 * i + 1];
        __half2 h0 = __floats2half2_rn(a.x, a.y);
        __half2 h1 = __floats2half2_rn(a.z, a.w);
        __half2 h2 = __floats2half2_rn(b.x, b.y);
        __half2 h3 = __floats2half2_rn(b.z, b.w);
        int4 packed;
        packed.x = *(const int*)&h0;
        packed.y = *(const int*)&h1;
        packed.z = *(const int*)&h2;
        packed.w = *(const int*)&h3;
        *reinterpret_cast<int4*>(&g_xh[4 * i]) = packed;
    }
    asm volatile("griddepcontrol.launch_dependents;" ::: "memory");
}

__device__ __forceinline__ void stg_cs_f4(float4* p, float4 v)
{
    asm volatile("st.global.cs.v4.f32 [%0], {%1,%2,%3,%4};"
                 :: "l"(p), "f"(v.x), "f"(v.y), "f"(v.z), "f"(v.w)
                 : "memory");
}

__global__ __launch_bounds__(256, 8)   // pin 32-reg budget -> full occupancy
void knn_mean_max_kernel(const int2* __restrict__ idx2,
                         float4*     __restrict__ out4,
                         int V)
{
    const int warp = (blockIdx.x * blockDim.x + threadIdx.x) >> 5;
    const int lane = threadIdx.x & 31;
    const int h    = lane >> 4;        // which vertex of the pair
    const int hl   = lane & 15;        // position within half-warp
    const int v    = 2 * warp + h;     // this half-warp's vertex
    const bool active = (v < V);

    // Coalesced idx load: half-warp hw loads its vertex's 32 idx as 16 int2
    // (lanes 0..31 cover 256B contiguous: idxs of vertices 2w and 2w+1).
    int2 pair = make_int2(0, 0);
    if (active) pair = idx2[v * (KNN / 2) + hl];

    // Block until convert's g_xh writes are visible.
    asm volatile("griddepcontrol.wait;" ::: "memory");

    if (!active) return;

    const __half2 zero = __float2half2_rn(0.0f);
    const __half2 ninf = __float2half2_rn(-65504.0f);
    __half2 sa0 = zero, sa1 = zero, sb0 = zero, sb1 = zero;  // 2x16 chains
    __half2 m0 = ninf, m1 = ninf;

    // Lane reads half2 pair (8B) at offset hl of each gathered row
    // (row = 32 half2 = 128B; 16 lanes * 8B cover it).
    const __half2* __restrict__ xl = g_xh + 2 * hl;
    const int srcbase = lane & 16;     // shuffles stay within the half-warp

    #pragma unroll
    for (int k = 0; k < KNN; ++k) {
        // idx[v][k] lives in lane (srcbase + k/2), component k&1 (compile-
        // time in the unrolled loop -> one SHFL of one register).
        const int idx = __shfl_sync(0xffffffffu,
                                    (k & 1) ? pair.y : pair.x,
                                    srcbase + (k >> 1));
        const __half2* p = xl + (size_t)(unsigned)idx * (FDIM / 2);
        unsigned int u0, u1;
        asm("ld.global.nc.v2.u32 {%0,%1}, [%2];" : "=r"(u0), "=r"(u1) : "l"(p));
        const __half2 ha = *(const __half2*)&u0;
        const __half2 hb = *(const __half2*)&u1;
        if (k & 1) { sb0 = __hadd2(sb0, ha); sb1 = __hadd2(sb1, hb); }
        else       { sa0 = __hadd2(sa0, ha); sa1 = __hadd2(sa1, hb); }
        m0 = __hmax2(m0, ha);
        m1 = __hmax2(m1, hb);
    }

    const float2 f0a = __half22float2(sa0), f0b = __half22float2(sb0);
    const float2 f1a = __half22float2(sa1), f1b = __half22float2(sb1);
    const float2 fm0 = __half22float2(m0),  fm1 = __half22float2(m1);
    const float inv = 1.0f / KNN;

    // Lane holds features [4*hl, 4*hl+4) of vertex v.
    // out row = 128 floats = 32 float4: [mean 16 float4 | max 16 float4].
    float4 mean = make_float4((f0a.x + f0b.x) * inv, (f0a.y + f0b.y) * inv,
                              (f1a.x + f1b.x) * inv, (f1a.y + f1b.y) * inv);
    float4 mx   = make_float4(fm0.x, fm0.y, fm1.x, fm1.y);

    stg_cs_f4(&out4[v * 32 + hl],      mean);
    stg_cs_f4(&out4[v * 32 + 16 + hl], mx);
}

extern "C" void kernel_launch(void* const* d_in, const int* in_sizes, int n_in,
                              void* d_out, int out_size)
{
    const float4* x4   = (const float4*)d_in[0];  // x: [V, 64] float32
    const int2*   idx2 = (const int2*)d_in[1];    // idxs: [V, 32] int32
    float4*       out4 = (float4*)d_out;          // out: [V, 128] float32

    const int V  = in_sizes[0] / FDIM;            // 100000
    const int n8 = in_sizes[0] / 8;               // V*F/8 (16B per thread)

    convert_kernel<<<(n8 + 255) / 256, 256>>>(x4, n8);

    const int warps = (V + 1) / 2;                // 2 vertices per warp
    const int blocks = (warps + 7) / 8;           // 8 warps per block

    cudaLaunchConfig_t cfg = {};
    cfg.gridDim  = dim3((unsigned)blocks, 1, 1);
    cfg.blockDim = dim3(256, 1, 1);
    cfg.dynamicSmemBytes = 0;
    cfg.stream = 0;

    cudaLaunchAttribute attrs[1];
    attrs[0].id = cudaLaunchAttributeProgrammaticStreamSerialization;
    attrs[0].val.programmaticStreamSerializationAllowed = 1;
    cfg.attrs = attrs;
    cfg.numAttrs = 1;

    cudaLaunchKernelEx(&cfg, knn_mean_max_kernel, idx2, out4, V);
}